// round 4
// baseline (speedup 1.0000x reference)
#include <cuda_runtime.h>
#include <math.h>
#include <float.h>

// Problem constants
#define NROWS   131072            // 16 * 8192
#define DIM     64
#define KCODES  1024
#define NLEVELS 4

// Output layout (float32): [quantized_out | codes (level-major, as float) | total_loss]
#define CODES_OFF 8388608         // NROWS * DIM
#define LOSS_OFF  8912896         // CODES_OFF + NLEVELS * NROWS

// Tiling
#define MB 64                     // rows per CTA
#define NC 128                    // codes per smem chunk
#define TM 4                      // rows per thread
#define TN 8                      // codes per thread (per chunk)
#define SK 66                     // smem k-stride: even (8B align), 66%32==2 -> conflict-free LDS.64

// Ambiguity threshold on score v = ||c||^2 - 2*dot. Worst-case reorder error of an
// fp32 64-term dot is ~3e-4 -> 6e-4 on v; 8e-3 gives >10x safety margin.
#define AMB_EPS 8e-3f

typedef unsigned long long ull;

#define FMA_F32X2(d, a, b) \
    asm("fma.rn.f32x2 %0, %1, %2, %0;" : "+l"(d) : "l"(a), "l"(b))

__device__ __align__(16) float g_residual[NROWS * DIM];
__device__ float g_cnorm[KCODES];
__device__ float g_counts[KCODES];
__device__ float g_sqerr;
__device__ float g_loss;

// Per-level prep: ||c||^2, zero counts/sqerr (and loss at level 0)
__global__ void prep_kernel(const float* __restrict__ cb, int level) {
    int c = blockIdx.x * blockDim.x + threadIdx.x;
    if (c < KCODES) {
        const float4* v = (const float4*)cb;
        float s = 0.f;
        #pragma unroll
        for (int t = 0; t < DIM / 4; t++) {
            float4 f = v[c * (DIM / 4) + t];
            s += f.x * f.x + f.y * f.y + f.z * f.z + f.w * f.w;
        }
        g_cnorm[c]  = s;
        g_counts[c] = 0.f;
    }
    if (blockIdx.x == 0 && threadIdx.x == 0) {
        g_sqerr = 0.f;
        if (level == 0) g_loss = 0.f;
    }
}

// Main fused kernel: packed-f32x2 argmin GEMM with second-best margin tracking,
// exact sequential-fp32 rescan for ambiguous rows, then residual/loss epilogue.
__global__ __launch_bounds__(256, 2) void rvq_main_kernel(
    const float* __restrict__ x0,        // original x
    const float* __restrict__ cb,        // this level's codebook [K][D]
    float* __restrict__ qout,            // d_out + 0 (written only at last level)
    float* __restrict__ codes_out,       // d_out + CODES_OFF + level*NROWS
    int level)
{
    extern __shared__ float sm[];
    float* As    = sm;                               // [MB][SK]
    float* Bs    = sm + MB * SK;                     // [NC][SK]
    int*   sBest = (int*)(sm + MB * SK + NC * SK);   // [MB]
    float* sRed  = (float*)(sBest + MB);             // [8]
    float* sRv   = sRed + 8;                         // [8]
    int*   sRi   = (int*)(sRv + 8);                  // [8]
    int*   sAmbRows = sRi + 8;                       // [MB]
    int*   sAmbCnt  = sAmbRows + MB;                 // [1]

    const int tid = threadIdx.x;
    const int tx  = tid & 15;
    const int ty  = tid >> 4;
    const size_t rowBase = (size_t)blockIdx.x * MB;

    const float* xin = (level == 0) ? x0 : g_residual;

    if (tid == 0) *sAmbCnt = 0;

    // Load A tile (MB rows x DIM) into smem, k-stride SK
    {
        const float4* src = (const float4*)(xin + rowBase * DIM);
        #pragma unroll
        for (int it = 0; it < 4; it++) {
            int v = tid + it * 256;        // 0..1023 float4 index
            int r = v >> 4, c = v & 15;
            float4 f = src[v];
            float2* d = (float2*)&As[r * SK + c * 4];
            d[0] = make_float2(f.x, f.y);
            d[1] = make_float2(f.z, f.w);
        }
    }

    float best[TM], best2[TM];
    int   bidx[TM];
    #pragma unroll
    for (int i = 0; i < TM; i++) { best[i] = FLT_MAX; best2[i] = FLT_MAX; bidx[i] = 0; }

    for (int ch = 0; ch < KCODES / NC; ch++) {
        __syncthreads();
        // Load B chunk (NC codes x DIM), k-stride SK
        {
            const float4* bsrc = (const float4*)(cb + (size_t)ch * NC * DIM);
            #pragma unroll
            for (int it = 0; it < 8; it++) {
                int v = tid + it * 256;
                int c = v >> 4, d4 = v & 15;
                float4 f = bsrc[v];
                float2* d = (float2*)&Bs[c * SK + d4 * 4];
                d[0] = make_float2(f.x, f.y);
                d[1] = make_float2(f.z, f.w);
            }
        }
        __syncthreads();

        // acc2: even-k partial in .lo, odd-k partial in .hi
        ull acc2[TM][TN];
        #pragma unroll
        for (int i = 0; i < TM; i++)
            #pragma unroll
            for (int j = 0; j < TN; j++) acc2[i][j] = 0ull;

        #pragma unroll 8
        for (int kp = 0; kp < DIM / 2; kp++) {
            const int k = kp * 2;
            ull a2[TM], b2[TN];
            #pragma unroll
            for (int i = 0; i < TM; i++)
                a2[i] = *(const ull*)&As[(i * 16 + ty) * SK + k];
            #pragma unroll
            for (int j = 0; j < TN; j++)
                b2[j] = *(const ull*)&Bs[(j * 16 + tx) * SK + k];
            #pragma unroll
            for (int i = 0; i < TM; i++)
                #pragma unroll
                for (int j = 0; j < TN; j++)
                    FMA_F32X2(acc2[i][j], a2[i], b2[j]);
        }

        // Fold into running (best, second-best): score = ||c||^2 - 2*(lo+hi)
        #pragma unroll
        for (int j = 0; j < TN; j++) {
            int code = ch * NC + j * 16 + tx;
            float cn = g_cnorm[code];
            #pragma unroll
            for (int i = 0; i < TM; i++) {
                float lo = __uint_as_float((unsigned)(acc2[i][j] & 0xffffffffu));
                float hi = __uint_as_float((unsigned)(acc2[i][j] >> 32));
                float v = fmaf(-2.f, lo + hi, cn);
                if (v < best[i]) {
                    best2[i] = best[i]; best[i] = v; bidx[i] = code;
                } else {
                    best2[i] = fminf(best2[i], v);
                }
            }
        }
    }

    // Cross-thread reduce of (best, idx, second-best) over the 16 tx-threads per row
    #pragma unroll
    for (int i = 0; i < TM; i++) {
        float v = best[i], s = best2[i]; int ix = bidx[i];
        #pragma unroll
        for (int off = 8; off >= 1; off >>= 1) {
            float v2 = __shfl_down_sync(0xffffffffu, v, off);
            float s2 = __shfl_down_sync(0xffffffffu, s, off);
            int   i2 = __shfl_down_sync(0xffffffffu, ix, off);
            float m  = fmaxf(v, v2);
            s = fminf(fminf(s, s2), m);
            if (v2 < v || (v2 == v && i2 < ix)) { v = v2; ix = i2; }
        }
        if (tx == 0) {
            int r = i * 16 + ty;
            sBest[r] = ix;
            if (s - v < AMB_EPS) {           // margin too small: exact rescan needed
                int slot = atomicAdd(sAmbCnt, 1);
                sAmbRows[slot] = r;
            }
        }
    }
    __syncthreads();

    // Exact rescan (round-1 sequential-fp32 order) for ambiguous rows — rare
    int nAmb = *sAmbCnt;
    for (int a = 0; a < nAmb; a++) {
        int r = sAmbRows[a];
        float bv = FLT_MAX; int bi = 0;
        #pragma unroll
        for (int cc = 0; cc < 4; cc++) {
            int code = tid + cc * 256;                    // increasing -> lowest idx wins ties
            const float4* cv = (const float4*)(cb + (size_t)code * DIM);
            float acc = 0.f;
            #pragma unroll
            for (int t = 0; t < DIM / 4; t++) {
                float4 f = cv[t];
                const float* ap = &As[r * SK + t * 4];
                acc = fmaf(ap[0], f.x, acc);
                acc = fmaf(ap[1], f.y, acc);
                acc = fmaf(ap[2], f.z, acc);
                acc = fmaf(ap[3], f.w, acc);
            }
            float v = fmaf(-2.f, acc, g_cnorm[code]);
            if (v < bv) { bv = v; bi = code; }
        }
        #pragma unroll
        for (int off = 16; off >= 1; off >>= 1) {
            float v2 = __shfl_down_sync(0xffffffffu, bv, off);
            int   i2 = __shfl_down_sync(0xffffffffu, bi, off);
            if (v2 < bv || (v2 == bv && i2 < bi)) { bv = v2; bi = i2; }
        }
        if ((tid & 31) == 0) { sRv[tid >> 5] = bv; sRi[tid >> 5] = bi; }
        __syncthreads();
        if (tid == 0) {
            float v = sRv[0]; int ix = sRi[0];
            #pragma unroll
            for (int w = 1; w < 8; w++)
                if (sRv[w] < v || (sRv[w] == v && sRi[w] < ix)) { v = sRv[w]; ix = sRi[w]; }
            sBest[r] = ix;
        }
        __syncthreads();
    }

    // Codes + histogram (after ambiguity resolution)
    if (tid < MB) {
        int ix = sBest[tid];
        codes_out[rowBase + tid] = (float)ix;
        atomicAdd(&g_counts[ix], 1.0f);
    }
    __syncthreads();

    // Epilogue: residual update + squared-error, coalesced float4; A still in smem
    float sq = 0.f;
    const float4* cb4  = (const float4*)cb;
    float4* res4       = (float4*)(g_residual + rowBase * DIM);
    const float4* x04  = (const float4*)(x0 + rowBase * DIM);
    float4* q4         = (float4*)(qout + rowBase * DIM);
    #pragma unroll
    for (int it = 0; it < 4; it++) {
        int v = tid + it * 256;
        int r = v >> 4, c = v & 15;
        int code = sBest[r];
        float4 q = cb4[code * (DIM / 4) + c];
        float* ap = &As[r * SK + c * 4];
        float4 rn;
        rn.x = ap[0] - q.x; rn.y = ap[1] - q.y;
        rn.z = ap[2] - q.z; rn.w = ap[3] - q.w;
        sq += rn.x * rn.x + rn.y * rn.y + rn.z * rn.z + rn.w * rn.w;
        res4[v] = rn;
        if (level == NLEVELS - 1) {
            float4 x = x04[v];
            float4 o;
            o.x = x.x - rn.x; o.y = x.y - rn.y;
            o.z = x.z - rn.z; o.w = x.w - rn.w;
            q4[v] = o;
        }
    }
    #pragma unroll
    for (int off = 16; off >= 1; off >>= 1)
        sq += __shfl_down_sync(0xffffffffu, sq, off);
    if ((tid & 31) == 0) sRed[tid >> 5] = sq;
    __syncthreads();
    if (tid == 0) {
        float s = 0.f;
        #pragma unroll
        for (int w = 0; w < 8; w++) s += sRed[w];
        atomicAdd(&g_sqerr, s);
    }
}

// Per-level loss finalize: entropy of usage histogram + (rec + commit) term
__global__ void finalize_kernel(float* __restrict__ loss_out, int level) {
    __shared__ float red[8];
    float ent = 0.f;
    for (int c = threadIdx.x; c < KCODES; c += 256) {
        float p = g_counts[c] * (1.0f / (float)NROWS);
        ent -= p * logf(p + 1e-10f);
    }
    #pragma unroll
    for (int off = 16; off >= 1; off >>= 1)
        ent += __shfl_down_sync(0xffffffffu, ent, off);
    if ((threadIdx.x & 31) == 0) red[threadIdx.x >> 5] = ent;
    __syncthreads();
    if (threadIdx.x == 0) {
        float e = 0.f;
        #pragma unroll
        for (int w = 0; w < 8; w++) e += red[w];
        g_loss += 1.25f * g_sqerr * (1.0f / (float)(NROWS * DIM)) + 0.1f * e;
        if (level == NLEVELS - 1) loss_out[0] = g_loss;
    }
}

extern "C" void kernel_launch(void* const* d_in, const int* in_sizes, int n_in,
                              void* d_out, int out_size) {
    const float* a0 = (const float*)d_in[0];
    const float* a1 = (const float*)d_in[1];
    const float* x;
    const float* cbs;
    if (in_sizes[0] == NLEVELS * KCODES * DIM) { cbs = a0; x = a1; }
    else                                        { x = a0; cbs = a1; }

    float* out = (float*)d_out;

    size_t smemBytes = (size_t)(MB * SK + NC * SK) * sizeof(float)
                     + MB * sizeof(int)          // sBest
                     + 8 * sizeof(float)         // sRed
                     + 8 * sizeof(float)         // sRv
                     + 8 * sizeof(int)           // sRi
                     + MB * sizeof(int)          // sAmbRows
                     + sizeof(int);              // sAmbCnt
    cudaFuncSetAttribute(rvq_main_kernel,
                         cudaFuncAttributeMaxDynamicSharedMemorySize,
                         (int)smemBytes);

    for (int l = 0; l < NLEVELS; l++) {
        const float* cb = cbs + (size_t)l * KCODES * DIM;
        prep_kernel<<<(KCODES + 255) / 256, 256>>>(cb, l);
        rvq_main_kernel<<<NROWS / MB, 256, smemBytes>>>(
            x, cb, out, out + CODES_OFF + (size_t)l * NROWS, l);
        finalize_kernel<<<1, 256>>>(out + LOSS_OFF, l);
    }
}